// round 8
// baseline (speedup 1.0000x reference)
#include <cuda_runtime.h>

// AutogradLoss, three-kernel structure:
//   K0 warm:      pure-read sweep of x,y -> populate L2 (134 MB vs 126 MB L2).
//                 No read<->write turnaround tax (pure-read phase @ ~7.3 TB/s).
//   K1 loss_grad: re-read x,y (mostly L2 hits) -> write loss=(x-y)^2,
//                 dloss=2(x-y) with __stcs (evict-first: stores recycle among
//                 themselves instead of displacing the warmed inputs).
//                 DRAM side is ~pure-write.
//   K2 hess:      sqd_loss = 2*I per sample, pure streaming writes (proven
//                 139us @ 91.8% DRAM).
// Output layout: [loss (B*16) | d_loss (B*16) | sqd_loss (B*256)] floats.

// ---- K0: L2 warm. Plain 128-bit loads (evict-normal). asm keeps loads live. ----
__global__ void __launch_bounds__(256) warm_kernel(
        const float4* __restrict__ x,
        const float4* __restrict__ y,
        int n4) {
    int i = blockIdx.x * blockDim.x + threadIdx.x;
    int stride = gridDim.x * blockDim.x;
    float acc = 0.0f;
    for (; i < n4; i += stride) {
        float4 a = x[i];
        float4 b = y[i];
        acc += a.x + b.x;          // dependency so loads can't be eliminated
    }
    asm volatile("" :: "f"(acc));  // consume; no memory side effects
}

// ---- K1: compute + write. Reads plain (hit L2), writes streaming. ----
__global__ void __launch_bounds__(256) loss_grad_kernel(
        const float4* __restrict__ x,
        const float4* __restrict__ y,
        float4* __restrict__ loss,
        float4* __restrict__ dloss,
        int n4) {
    int base = blockIdx.x * (256 * 4) + threadIdx.x;
    #pragma unroll
    for (int j = 0; j < 4; j++) {
        int idx = base + j * 256;
        if (idx < n4) {
            float4 a = x[idx];             // plain: L2 hit from warm
            float4 b = y[idx];
            float dx = a.x - b.x, dy = a.y - b.y;
            float dz = a.z - b.z, dw = a.w - b.w;
            __stcs(&loss[idx],  make_float4(dx * dx, dy * dy, dz * dz, dw * dw));
            __stcs(&dloss[idx], make_float4(2.f * dx, 2.f * dy, 2.f * dz, 2.f * dw));
        }
    }
}

// ---- K2: pure-write 2*I pattern (R4 form). ----
// f4 index i: within-sample f4 pos = i&63; flat offset s0 = pos*4;
// row = s0>>4, col0 = s0&15; element e is 2.0 iff row == col0+e.
__global__ void __launch_bounds__(256) hess_kernel(float4* __restrict__ sq,
                                                   long long n4) {
    long long base = (long long)blockIdx.x * (256 * 8) + threadIdx.x;
    #pragma unroll
    for (int j = 0; j < 8; j++) {
        long long i = base + j * 256;
        if (i < n4) {
            int s0 = ((int)i & 63) << 2;
            int row = s0 >> 4;
            int col0 = s0 & 15;
            float4 v;
            v.x = (row == col0)     ? 2.0f : 0.0f;
            v.y = (row == col0 + 1) ? 2.0f : 0.0f;
            v.z = (row == col0 + 2) ? 2.0f : 0.0f;
            v.w = (row == col0 + 3) ? 2.0f : 0.0f;
            __stcs(&sq[i], v);
        }
    }
}

extern "C" void kernel_launch(void* const* d_in, const int* in_sizes, int n_in,
                              void* d_out, int out_size) {
    const float* x = (const float*)d_in[0];
    const float* y = (const float*)d_in[1];
    float* out = (float*)d_out;

    long long bd = in_sizes[0];          // B*16 floats
    long long n4_ld = bd / 4;            // float4 for loss / d_loss
    long long n4_sq = bd * 4;            // float4 for sqd_loss (bd*16/4)

    float* loss  = out;
    float* dloss = out + bd;
    float* sq    = out + 2 * bd;

    {
        // Warm: enough blocks to saturate read BW; grid-stride.
        warm_kernel<<<2048, 256>>>((const float4*)x, (const float4*)y,
                                   (int)n4_ld);
    }
    {
        long long per_block = 256LL * 4;
        int blocks = (int)((n4_ld + per_block - 1) / per_block);
        loss_grad_kernel<<<blocks, 256>>>((const float4*)x, (const float4*)y,
                                          (float4*)loss, (float4*)dloss,
                                          (int)n4_ld);
    }
    {
        long long per_block = 256LL * 8;
        int blocks = (int)((n4_sq + per_block - 1) / per_block);
        hess_kernel<<<blocks, 256>>>((float4*)sq, n4_sq);
    }
}

// round 9
// speedup vs baseline: 1.0109x; 1.0109x over previous
#include <cuda_runtime.h>

// AutogradLoss, three-kernel structure:
//   K0 warm:      prefetch.global.L2 sweep of first 7/8 of x,y (117 MB < 126 MB
//                 L2). Pure-read DRAM phase, no turnaround tax. PTX prefetch
//                 cannot be dead-code-eliminated (R8's load-based warm was).
//   K1 loss_grad: read x,y via __ldcs (mostly L2 hits; misses evict-first) ->
//                 write loss=(x-y)^2, dloss=2(x-y) via __stcs. DRAM ~pure-write.
//   K2 hess:      sqd_loss = 2*I per sample, pure streaming writes (139us @ 91.8%).
// Output layout: [loss (B*16) | d_loss (B*16) | sqd_loss (B*256)] floats.

// ---- K0: L2 prefetch warm. One prefetch per 128B line. ----
__global__ void __launch_bounds__(256) warm_kernel(
        const char* __restrict__ x,
        const char* __restrict__ y,
        long long warm_lines) {           // 128B lines per tensor to prefetch
    long long i = (long long)blockIdx.x * blockDim.x + threadIdx.x;
    long long stride = (long long)gridDim.x * blockDim.x;
    for (; i < warm_lines; i += stride) {
        const char* px = x + i * 128;
        const char* py = y + i * 128;
        asm volatile("prefetch.global.L2 [%0];" :: "l"(px) : "memory");
        asm volatile("prefetch.global.L2 [%0];" :: "l"(py) : "memory");
    }
}

// ---- K1: compute + write. Streaming reads (hit L2 from warm), streaming writes. ----
__global__ void __launch_bounds__(256) loss_grad_kernel(
        const float4* __restrict__ x,
        const float4* __restrict__ y,
        float4* __restrict__ loss,
        float4* __restrict__ dloss,
        int n4) {
    int base = blockIdx.x * (256 * 4) + threadIdx.x;
    #pragma unroll
    for (int j = 0; j < 4; j++) {
        int idx = base + j * 256;
        if (idx < n4) {
            float4 a = __ldcs(&x[idx]);
            float4 b = __ldcs(&y[idx]);
            float dx = a.x - b.x, dy = a.y - b.y;
            float dz = a.z - b.z, dw = a.w - b.w;
            __stcs(&loss[idx],  make_float4(dx * dx, dy * dy, dz * dz, dw * dw));
            __stcs(&dloss[idx], make_float4(2.f * dx, 2.f * dy, 2.f * dz, 2.f * dw));
        }
    }
}

// ---- K2: pure-write 2*I pattern (proven R4 form). ----
// f4 index i: within-sample f4 pos = i&63; flat offset s0 = pos*4;
// row = s0>>4, col0 = s0&15; element e is 2.0 iff row == col0+e.
__global__ void __launch_bounds__(256) hess_kernel(float4* __restrict__ sq,
                                                   long long n4) {
    long long base = (long long)blockIdx.x * (256 * 8) + threadIdx.x;
    #pragma unroll
    for (int j = 0; j < 8; j++) {
        long long i = base + j * 256;
        if (i < n4) {
            int s0 = ((int)i & 63) << 2;
            int row = s0 >> 4;
            int col0 = s0 & 15;
            float4 v;
            v.x = (row == col0)     ? 2.0f : 0.0f;
            v.y = (row == col0 + 1) ? 2.0f : 0.0f;
            v.z = (row == col0 + 2) ? 2.0f : 0.0f;
            v.w = (row == col0 + 3) ? 2.0f : 0.0f;
            __stcs(&sq[i], v);
        }
    }
}

extern "C" void kernel_launch(void* const* d_in, const int* in_sizes, int n_in,
                              void* d_out, int out_size) {
    const float* x = (const float*)d_in[0];
    const float* y = (const float*)d_in[1];
    float* out = (float*)d_out;

    long long bd = in_sizes[0];          // B*16 floats
    long long n4_ld = bd / 4;            // float4 for loss / d_loss
    long long n4_sq = bd * 4;            // float4 for sqd_loss (bd*16/4)

    float* loss  = out;
    float* dloss = out + bd;
    float* sq    = out + 2 * bd;

    {
        long long lines = (bd * 4) / 128;          // 128B lines per tensor
        long long warm_lines = (lines * 7) / 8;    // warm 7/8 (117 MB of 134 MB)
        warm_kernel<<<1024, 256>>>((const char*)x, (const char*)y, warm_lines);
    }
    {
        long long per_block = 256LL * 4;
        int blocks = (int)((n4_ld + per_block - 1) / per_block);
        loss_grad_kernel<<<blocks, 256>>>((const float4*)x, (const float4*)y,
                                          (float4*)loss, (float4*)dloss,
                                          (int)n4_ld);
    }
    {
        long long per_block = 256LL * 8;
        int blocks = (int)((n4_sq + per_block - 1) / per_block);
        hess_kernel<<<blocks, 256>>>((float4*)sq, n4_sq);
    }
}

// round 10
// speedup vs baseline: 1.0182x; 1.0072x over previous
#include <cuda_runtime.h>

// AutogradLoss — converged form (R3, measured best 182.3us):
//   loss = (x-y)^2, d_loss = 2(x-y), sqd_loss = 2*I per sample (constant).
// Output layout: [loss (B*16) | d_loss (B*16) | sqd_loss (B*256)] floats.
//
// Structure: two serial kernels.
//   K1 loss_grad (268 MB mixed R/W)  -> pinned at mixed-phase ceiling 6.2 TB/s
//      (invariant under ILP 1/4/8, ldcs/stcs hints, burst batching: R4/R6)
//   K2 hess (1.074 GB pure write)    -> pinned at write wall 7.73 TB/s, 91.8% DRAM
// Falsified alternatives: fused single stream (R5: -11% DRAM eff), L2 writeback
// deferral (R7), L2 pre-warm via loads (R8) and prefetch.global.L2 (R9).

__global__ void loss_grad_kernel(const float4* __restrict__ x,
                                 const float4* __restrict__ y,
                                 float4* __restrict__ loss,
                                 float4* __restrict__ dloss,
                                 int n4) {
    int i = blockIdx.x * blockDim.x + threadIdx.x;
    if (i < n4) {
        float4 a = x[i];
        float4 b = y[i];
        float dx = a.x - b.x, dy = a.y - b.y, dz = a.z - b.z, dw = a.w - b.w;
        float4 l, g;
        l.x = dx * dx; l.y = dy * dy; l.z = dz * dz; l.w = dw * dw;
        g.x = 2.f * dx; g.y = 2.f * dy; g.z = 2.f * dz; g.w = 2.f * dw;
        loss[i]  = l;
        dloss[i] = g;
    }
}

// sqd_loss[b] is a 16x16 matrix = 2*I. Per sample: 256 floats = 64 float4.
// float4 index pos in [0,64): row = pos>>2, col-group = pos&3.
// The diagonal element (row,row) lives in col-group row>>2, lane row&3.
__global__ void hess_kernel(float4* __restrict__ sq, long long n4) {
    long long i = (long long)blockIdx.x * blockDim.x + threadIdx.x;
    if (i < n4) {
        int pos = (int)(i & 63);
        int row = pos >> 2;
        int grp = pos & 3;
        float4 v = make_float4(0.f, 0.f, 0.f, 0.f);
        if (grp == (row >> 2)) {
            ((float*)&v)[row & 3] = 2.0f;
        }
        sq[i] = v;
    }
}

extern "C" void kernel_launch(void* const* d_in, const int* in_sizes, int n_in,
                              void* d_out, int out_size) {
    const float* x = (const float*)d_in[0];
    const float* y = (const float*)d_in[1];
    float* out = (float*)d_out;

    long long bd = in_sizes[0];          // B*16
    long long n4_ld = bd / 4;            // float4 count for loss / d_loss
    long long n4_sq = bd * 16 / 4;       // float4 count for sqd_loss

    float* loss  = out;
    float* dloss = out + bd;
    float* sq    = out + 2 * bd;

    {
        int threads = 256;
        int blocks = (int)((n4_ld + threads - 1) / threads);
        loss_grad_kernel<<<blocks, threads>>>((const float4*)x, (const float4*)y,
                                              (float4*)loss, (float4*)dloss,
                                              (int)n4_ld);
    }
    {
        int threads = 256;
        int blocks = (int)((n4_sq + threads - 1) / threads);
        hess_kernel<<<blocks, threads>>>((float4*)sq, n4_sq);
    }
}

// round 11
// speedup vs baseline: 1.0225x; 1.0042x over previous
#include <cuda_runtime.h>

// AutogradLoss — CONVERGED (measured best 182.3us, noise band ±0.8us):
//   loss = (x-y)^2, d_loss = 2(x-y), sqd_loss = 2*I per sample (constant).
// Output layout: [loss (B*16) | d_loss (B*16) | sqd_loss (B*256)] floats.
//
// Structure: two serial kernels — proven optimal:
//   K1 loss_grad (268 MB mixed R/W)  @ mixed-phase ceiling 6.2 TB/s
//      (invariant under ILP 1/4/8, cache hints, burst batching: R4/R6)
//   K2 hess (1.074 GB pure write)    @ write wall 7.73 TB/s, ~92% DRAM
//      (invariant under occupancy 50%->93%: pure DRAM limit)
// Falsified: fusion (R5: -11% DRAM eff), L2 writeback deferral (R7),
// L2 pre-warm via loads (R8) and prefetch.global.L2 (R9).
// Floor under measured ceilings = 139 + 43 = 182us = achieved.

__global__ void loss_grad_kernel(const float4* __restrict__ x,
                                 const float4* __restrict__ y,
                                 float4* __restrict__ loss,
                                 float4* __restrict__ dloss,
                                 int n4) {
    int i = blockIdx.x * blockDim.x + threadIdx.x;
    if (i < n4) {
        float4 a = x[i];
        float4 b = y[i];
        float dx = a.x - b.x, dy = a.y - b.y, dz = a.z - b.z, dw = a.w - b.w;
        float4 l, g;
        l.x = dx * dx; l.y = dy * dy; l.z = dz * dz; l.w = dw * dw;
        g.x = 2.f * dx; g.y = 2.f * dy; g.z = 2.f * dz; g.w = 2.f * dw;
        loss[i]  = l;
        dloss[i] = g;
    }
}

// sqd_loss[b] is a 16x16 matrix = 2*I. Per sample: 256 floats = 64 float4.
// float4 index pos in [0,64): row = pos>>2, col-group = pos&3.
// The diagonal element (row,row) lives in col-group row>>2, lane row&3.
__global__ void hess_kernel(float4* __restrict__ sq, long long n4) {
    long long i = (long long)blockIdx.x * blockDim.x + threadIdx.x;
    if (i < n4) {
        int pos = (int)(i & 63);
        int row = pos >> 2;
        int grp = pos & 3;
        float4 v = make_float4(0.f, 0.f, 0.f, 0.f);
        if (grp == (row >> 2)) {
            ((float*)&v)[row & 3] = 2.0f;
        }
        sq[i] = v;
    }
}

extern "C" void kernel_launch(void* const* d_in, const int* in_sizes, int n_in,
                              void* d_out, int out_size) {
    const float* x = (const float*)d_in[0];
    const float* y = (const float*)d_in[1];
    float* out = (float*)d_out;

    long long bd = in_sizes[0];          // B*16
    long long n4_ld = bd / 4;            // float4 count for loss / d_loss
    long long n4_sq = bd * 16 / 4;       // float4 count for sqd_loss

    float* loss  = out;
    float* dloss = out + bd;
    float* sq    = out + 2 * bd;

    {
        int threads = 256;
        int blocks = (int)((n4_ld + threads - 1) / threads);
        loss_grad_kernel<<<blocks, threads>>>((const float4*)x, (const float4*)y,
                                              (float4*)loss, (float4*)dloss,
                                              (int)n4_ld);
    }
    {
        int threads = 256;
        int blocks = (int)((n4_sq + threads - 1) / threads);
        hess_kernel<<<blocks, threads>>>((float4*)sq, n4_sq);
    }
}